// round 14
// baseline (speedup 1.0000x reference)
#include <cuda_runtime.h>
#include <cuda_fp16.h>
#include <math.h>
#include <stdint.h>

// Problem constants
#define BB    2
#define TT    2048
#define CC    512
#define HH    8
#define DD    64
#define C3    1536
#define KSEL  4
#define GAMMA_F 2.5f
#define RHO_F   0.085f
#define TAUCLIP 5.0f
#define NROW  (BB*TT)       // 4096
#define KTOT  512

typedef unsigned long long ull;

// ---------------- scratch (device globals) ---------------------------------
__device__ float g_qkv[(size_t)NROW * C3];        // 24 MB fp32
// fp16 operands
__device__ __half g_x_h[(size_t)NROW * KTOT];     // x (fp16)
__device__ __half g_wqt[(size_t)C3 * KTOT];       // Wqkv^T fp16
__device__ __half g_wpt[(size_t)CC * KTOT];       // Wproj^T fp16
__device__ __half g_ao[(size_t)NROW * KTOT];      // attn_out fp16

// ===================== helpers ==============================================
__device__ __forceinline__ uint32_t smem_u32(const void* p) {
    uint32_t a;
    asm("{ .reg .u64 t; cvta.to.shared.u64 t, %1; cvt.u32.u64 %0, t; }" : "=r"(a) : "l"(p));
    return a;
}
__device__ __forceinline__ void ldsm_x4(uint32_t& r0, uint32_t& r1, uint32_t& r2, uint32_t& r3,
                                        uint32_t addr) {
    asm volatile("ldmatrix.sync.aligned.m8n8.x4.shared.b16 {%0,%1,%2,%3}, [%4];"
                 : "=r"(r0), "=r"(r1), "=r"(r2), "=r"(r3) : "r"(addr));
}
__device__ __forceinline__ void mma_fp16(float* d, const uint32_t* a, uint32_t b0, uint32_t b1) {
    asm("mma.sync.aligned.m16n8k16.row.col.f32.f16.f16.f32 "
        "{%0,%1,%2,%3}, {%4,%5,%6,%7}, {%8,%9}, {%0,%1,%2,%3};"
        : "+f"(d[0]), "+f"(d[1]), "+f"(d[2]), "+f"(d[3])
        : "r"(a[0]), "r"(a[1]), "r"(a[2]), "r"(a[3]), "r"(b0), "r"(b1));
}

// ===================== operand prep (vectorized) ============================
__global__ void convert_h(const float* __restrict__ in,
                          __half* __restrict__ hi, int n4) {
    int i = blockIdx.x * 256 + threadIdx.x;     // float4 index
    if (i < n4) {
        float4 v = reinterpret_cast<const float4*>(in)[i];
        reinterpret_cast<__half2*>(hi)[i * 2]     = __floats2half2_rn(v.x, v.y);
        reinterpret_cast<__half2*>(hi)[i * 2 + 1] = __floats2half2_rn(v.z, v.w);
    }
}

// W [K,N] fp32 -> [N,K] fp16
__global__ void transpose_half(const float* __restrict__ W,
                               __half* __restrict__ out, int K, int N) {
    __shared__ float tile[32][33];
    int n0 = blockIdx.x * 32, k0 = blockIdx.y * 32;
    int tx = threadIdx.x, ty = threadIdx.y;
    #pragma unroll
    for (int i = 0; i < 32; i += 8)
        tile[ty + i][tx] = W[(size_t)(k0 + ty + i) * N + n0 + tx];
    __syncthreads();
    #pragma unroll
    for (int i = 0; i < 32; i += 8)
        out[(size_t)(n0 + ty + i) * K + k0 + tx] = __float2half(tile[tx][ty + i]);
}

// ===================== K64 / 2-stage / swizzled GEMM core (BM=64) ===========
// BM=64, BN=128, 8 warps (4m x 2n), warp tile 16x64.  Tiles: rows x 128B,
// XOR swizzle: unit' = unit ^ (row & 7).  occ 3 target.
#define A64_TILE 8192                // 64 rows x 128 B
#define B64_TILE 16384               // 128 rows x 128 B
#define G64_STAGE (A64_TILE + B64_TILE)       // A, B = 24576
#define G64_SMEM (2 * G64_STAGE)     // 49152
#define G64_NCH 8                    // 512 / 64

__device__ __forceinline__ void g64_load(
    uint32_t sm_base, int stage, int c, int m0, int n0, int tid,
    const __half* __restrict__ Ah, const __half* __restrict__ Bh)
{
    if (c < G64_NCH) {
        uint32_t sbase = sm_base + stage * G64_STAGE;
        const int k0 = c * 64;
        #pragma unroll
        for (int i = 0; i < 2; i++) {            // A: 64 rows x 8 units
            int u = tid + i * 256;
            int r = u >> 3, cu = u & 7;
            const void* gp = Ah + (size_t)(m0 + r) * KTOT + k0 + cu * 8;
            uint32_t dst = sbase + r * 128 + ((cu ^ (r & 7)) << 4);
            asm volatile("cp.async.cg.shared.global [%0], [%1], 16;" :: "r"(dst), "l"(gp));
        }
        #pragma unroll
        for (int i = 0; i < 4; i++) {            // B: 128 rows x 8 units
            int u = tid + i * 256;
            int r = u >> 3, cu = u & 7;
            const void* gp = Bh + (size_t)(n0 + r) * KTOT + k0 + cu * 8;
            uint32_t dst = sbase + A64_TILE + r * 128 + ((cu ^ (r & 7)) << 4);
            asm volatile("cp.async.cg.shared.global [%0], [%1], 16;" :: "r"(dst), "l"(gp));
        }
    }
    asm volatile("cp.async.commit_group;" ::: "memory");
}

__device__ __forceinline__ void gemm64_body(
    uint32_t sm_base, int m0, int n0, int tid,
    const __half* __restrict__ Ah, const __half* __restrict__ Bh,
    const float* __restrict__ bias, float* __restrict__ Cout, int N_out)
{
    const int wid = tid >> 5, lane = tid & 31;
    const int wm = wid >> 1, wn = wid & 1;       // 4m x 2n, warp tile 16x64

    float acc[8][4];
    #pragma unroll
    for (int j = 0; j < 8; j++)
        #pragma unroll
        for (int l = 0; l < 4; l++) acc[j][l] = 0.f;

    g64_load(sm_base, 0, 0, m0, n0, tid, Ah, Bh);
    g64_load(sm_base, 1, 1, m0, n0, tid, Ah, Bh);

    const int lrow = lane & 15;
    const int lu8 = (lane >> 4);

    for (int c = 0; c < G64_NCH; c++) {
        asm volatile("cp.async.wait_group 1;" ::: "memory");
        __syncthreads();
        const uint32_t stg = sm_base + (c & 1) * G64_STAGE;

        #pragma unroll
        for (int kk = 0; kk < 4; kk++) {
            const int ubase = kk * 2 + lu8;
            uint32_t ah[4], bh[4][4];
            {
                int r = wm * 16 + lrow;
                uint32_t ra = stg + r * 128 + ((ubase ^ (r & 7)) << 4);
                ldsm_x4(ah[0], ah[1], ah[2], ah[3], ra);
            }
            #pragma unroll
            for (int jn = 0; jn < 4; jn++) {
                int r = wn * 64 + jn * 16 + lrow;
                uint32_t rb = stg + A64_TILE + r * 128 + ((ubase ^ (r & 7)) << 4);
                ldsm_x4(bh[jn][0], bh[jn][1], bh[jn][2], bh[jn][3], rb);
            }
            #pragma unroll
            for (int jn = 0; jn < 4; jn++) {
                mma_fp16(acc[jn * 2],     ah, bh[jn][0], bh[jn][2]);
                mma_fp16(acc[jn * 2 + 1], ah, bh[jn][1], bh[jn][3]);
            }
        }
        __syncthreads();
        g64_load(sm_base, c & 1, c + 2, m0, n0, tid, Ah, Bh);
    }

    {
        int rbase = m0 + wm * 16 + (lane >> 2);
        #pragma unroll
        for (int jf = 0; jf < 8; jf++) {
            int col = n0 + wn * 64 + jf * 8 + (lane & 3) * 2;
            float2 b2 = *reinterpret_cast<const float2*>(bias + col);
            float2 o0, o1;
            o0.x = acc[jf][0] + b2.x; o0.y = acc[jf][1] + b2.y;
            o1.x = acc[jf][2] + b2.x; o1.y = acc[jf][3] + b2.y;
            *reinterpret_cast<float2*>(Cout + (size_t)rbase * N_out + col) = o0;
            *reinterpret_cast<float2*>(Cout + (size_t)(rbase + 8) * N_out + col) = o1;
        }
    }
}

// QKV: single fp16.
__global__ __launch_bounds__(256, 3) void qkv_gemm64(
    const __half* __restrict__ Ah, const __half* __restrict__ Bh,
    const float* __restrict__ bias, float* __restrict__ Cout)
{
    extern __shared__ char smem[];
    const uint32_t sm_base = smem_u32(smem);
    gemm64_body(sm_base, blockIdx.y * 64, blockIdx.x * 128, threadIdx.x,
                Ah, Bh, bias, Cout, C3);
}

// proj: single fp16.
__global__ __launch_bounds__(256, 3) void proj_gemm64(
    const __half* __restrict__ Ah, const __half* __restrict__ Bh,
    const float* __restrict__ bias, float* __restrict__ Cout)
{
    extern __shared__ char smem[];
    const uint32_t sm_base = smem_u32(smem);
    gemm64_body(sm_base, blockIdx.y * 64, blockIdx.x * 128, threadIdx.x,
                Ah, Bh, bias, Cout, CC);
}

// ===================== fused topk + attention + tau_new =====================
// 512 threads/row: each thread owns ONE float4 of the tau row (halves the
// serial insert chain), 16-warp tournament topk, warps 0-7 do attention.
__global__ __launch_bounds__(512) void attn_topk_fused(const float* __restrict__ tau,
                                                       float* __restrict__ out_tau) {
    const int row = blockIdx.x;
    const int tid = threadIdx.x;
    const int warp = tid >> 5, lane = tid & 31;
    const int b = row / TT;

    __shared__ ull   swk[16 * 4];                 // per-warp top4
    __shared__ float sred[16];
    __shared__ float srowsum;
    __shared__ int   sidx[KSEL];
    __shared__ float sbias[KSEL];
    __shared__ float stval[KSEL];
    __shared__ float ssig[KSEL];
    __shared__ float sinv;

    // ---- load tau row (1 float4/thread) + per-thread top4 + sum ----
    const float4* tin = reinterpret_cast<const float4*>(tau + (size_t)row * TT);
    float4 v = tin[tid];
    float sum = (v.x + v.y) + (v.z + v.w);

    ull k0 = 0, k1 = 0, k2 = 0, k3 = 0;
    #define TK_INS(val, col) do { \
        ull key = ((ull)__float_as_uint(val) << 32) | (unsigned)(0x7FFFFFFF - (col)); \
        if (key > k3) { \
            if (key > k0)      { k3 = k2; k2 = k1; k1 = k0; k0 = key; } \
            else if (key > k1) { k3 = k2; k2 = k1; k1 = key; } \
            else if (key > k2) { k3 = k2; k2 = key; } \
            else               { k3 = key; } \
        } } while (0)
    {
        int c0 = tid * 4;
        TK_INS(v.x, c0);     TK_INS(v.y, c0 + 1);
        TK_INS(v.z, c0 + 2); TK_INS(v.w, c0 + 3);
    }
    #undef TK_INS

    // ---- warp top-4: 4-round argmax tournament (keys unique) ----
    ull t0, t1, t2, t3;
    {
        ull h = k0;
        #pragma unroll
        for (int r = 0; r < 4; r++) {
            ull m = h;
            #pragma unroll
            for (int o = 16; o > 0; o >>= 1) {
                ull bb = __shfl_xor_sync(0xffffffffu, m, o);
                if (bb > m) m = bb;
            }
            if (r == 0) t0 = m; else if (r == 1) t1 = m;
            else if (r == 2) t2 = m; else t3 = m;
            if (h == m) { h = k1; k1 = k2; k2 = k3; k3 = 0; }  // unique winner pops
        }
    }
    #pragma unroll
    for (int o = 16; o > 0; o >>= 1) sum += __shfl_xor_sync(0xffffffffu, sum, o);

    if (lane == 0) {
        swk[warp * 4 + 0] = t0; swk[warp * 4 + 1] = t1;
        swk[warp * 4 + 2] = t2; swk[warp * 4 + 3] = t3;
        sred[warp] = sum;
    }
    __syncthreads();

    // ---- warp 0: tournament over the 16 per-warp lists (replicated x2) ----
    if (warp == 0) {
        int src = lane & 15;
        ull l0 = swk[src * 4], l1 = swk[src * 4 + 1];
        ull l2 = swk[src * 4 + 2], l3 = swk[src * 4 + 3];
        ull m0, m1, m2, m3;
        {
            ull h = l0;
            #pragma unroll
            for (int r = 0; r < 4; r++) {
                ull m = h;
                #pragma unroll
                for (int o = 8; o > 0; o >>= 1) {       // within replicated 16-group
                    ull bb = __shfl_xor_sync(0xffffffffu, m, o);
                    if (bb > m) m = bb;
                }
                if (r == 0) m0 = m; else if (r == 1) m1 = m;
                else if (r == 2) m2 = m; else m3 = m;
                if (h == m) { h = l1; l1 = l2; l2 = l3; l3 = 0; }
            }
        }
        float rs = sred[src];
        rs += __shfl_xor_sync(0xffffffffu, rs, 1);
        rs += __shfl_xor_sync(0xffffffffu, rs, 2);
        rs += __shfl_xor_sync(0xffffffffu, rs, 4);
        rs += __shfl_xor_sync(0xffffffffu, rs, 8);
        if (lane < KSEL) {
            ull key = (lane == 0) ? m0 : (lane == 1) ? m1 : (lane == 2) ? m2 : m3;
            int id = 0x7FFFFFFF - (int)(key & 0xFFFFFFFFu);
            float tv = __uint_as_float((unsigned)(key >> 32));
            sidx[lane]  = id;
            stval[lane] = tv;
            sbias[lane] = GAMMA_F * logf(tv + 1e-8f);
            ssig[lane]  = 0.f;
        }
        if (lane == 0) srowsum = rs;
    }
    __syncthreads();

    // ---- sparse attention (warps 0-7, warp == head) ----
    if (tid < 256) {
        const float* qp = g_qkv + (size_t)row * C3 + warp * DD;
        const float q0 = qp[lane], q1 = qp[lane + 32];

        float logit[KSEL];
        #pragma unroll
        for (int j = 0; j < KSEL; j++) {
            int s = sidx[j];
            const float* kp = g_qkv + (size_t)(b * TT + s) * C3 + CC + warp * DD;
            float p = q0 * kp[lane] + q1 * kp[lane + 32];
            #pragma unroll
            for (int o = 16; o > 0; o >>= 1) p += __shfl_xor_sync(0xffffffffu, p, o);
            logit[j] = p * 0.125f + sbias[j];
        }
        float m = fmaxf(fmaxf(logit[0], logit[1]), fmaxf(logit[2], logit[3]));
        float e[KSEL], se = 0.f;
        #pragma unroll
        for (int j = 0; j < KSEL; j++) { e[j] = expf(logit[j] - m); se += e[j]; }
        float inv = 1.f / se;
        float w[KSEL];
        #pragma unroll
        for (int j = 0; j < KSEL; j++) w[j] = e[j] * inv;

        float o0 = 0.f, o1 = 0.f;
        #pragma unroll
        for (int j = 0; j < KSEL; j++) {
            const float* vp = g_qkv + (size_t)(b * TT + sidx[j]) * C3 + 2 * CC + warp * DD;
            o0 = fmaf(w[j], vp[lane], o0);
            o1 = fmaf(w[j], vp[lane + 32], o1);
        }
        size_t obase = (size_t)row * KTOT + warp * DD;
        g_ao[obase + lane]      = __float2half(o0);
        g_ao[obase + lane + 32] = __float2half(o1);

        if (lane == 0) {
            #pragma unroll
            for (int j = 0; j < KSEL; j++) atomicAdd(&ssig[j], w[j] * (1.0f / HH));
        }
    }
    __syncthreads();
    if (tid == 0) {
        float rs = srowsum * (1.0f - RHO_F);
        #pragma unroll
        for (int j = 0; j < KSEL; j++) { float s = ssig[j]; rs += s * s * s; }
        sinv = 1.f / (rs + 1e-8f);
    }
    __syncthreads();

    // ---- tau_new: scale from registers + patch ----
    const float f = (1.0f - RHO_F) * sinv;
    float4 w0;
    w0.x = fminf(v.x * f, TAUCLIP); w0.y = fminf(v.y * f, TAUCLIP);
    w0.z = fminf(v.z * f, TAUCLIP); w0.w = fminf(v.w * f, TAUCLIP);
    reinterpret_cast<float4*>(out_tau + (size_t)row * TT)[tid] = w0;
    __syncthreads();
    if (tid < KSEL) {
        float s = ssig[tid];
        float vv = stval[tid] * (1.0f - RHO_F) + s * s * s;
        out_tau[(size_t)row * TT + sidx[tid]] = fminf(vv * sinv, TAUCLIP);
    }
}

// ===================== launch ===============================================
extern "C" void kernel_launch(void* const* d_in, const int* in_sizes, int n_in,
                              void* d_out, int out_size) {
    const float* x     = (const float*)d_in[0];
    const float* tau   = (const float*)d_in[1];
    const float* Wqkv  = (const float*)d_in[2];
    const float* bqkv  = (const float*)d_in[3];
    const float* Wproj = (const float*)d_in[4];
    const float* bproj = (const float*)d_in[5];

    float* out_main = (float*)d_out;
    float* out_tau  = out_main + (size_t)NROW * CC;

    void *p_qkv, *p_xh, *p_wqt, *p_wpt, *p_ao;
    cudaGetSymbolAddress(&p_qkv, g_qkv);
    cudaGetSymbolAddress(&p_xh, g_x_h);
    cudaGetSymbolAddress(&p_wqt, g_wqt);  cudaGetSymbolAddress(&p_wpt, g_wpt);
    cudaGetSymbolAddress(&p_ao, g_ao);

    cudaFuncSetAttribute(qkv_gemm64, cudaFuncAttributeMaxDynamicSharedMemorySize, G64_SMEM);
    cudaFuncSetAttribute(proj_gemm64, cudaFuncAttributeMaxDynamicSharedMemorySize, G64_SMEM);

    // 1-2. prep needed for QKV
    convert_h<<<(NROW * KTOT / 4) / 256, 256>>>(x, (__half*)p_xh, NROW * KTOT / 4);
    transpose_half<<<dim3(C3 / 32, KTOT / 32), dim3(32, 8)>>>(Wqkv, (__half*)p_wqt, KTOT, C3);

    // 3. QKV GEMM (single fp16, BM=64, occ 3): 768 CTAs
    qkv_gemm64<<<dim3(12, NROW / 64), 256, G64_SMEM>>>(
        (const __half*)p_xh, (const __half*)p_wqt, bqkv, (float*)p_qkv);

    // 4. fused: topk + sparse attention + tau_new (512 thr)  (launch #4 -> profiled)
    attn_topk_fused<<<NROW, 512>>>(tau, out_tau);

    // 5. Wproj transpose
    transpose_half<<<dim3(CC / 32, KTOT / 32), dim3(32, 8)>>>(Wproj, (__half*)p_wpt, KTOT, CC);

    // 6. proj GEMM (single fp16, BM=64): 256 CTAs, single wave
    proj_gemm64<<<dim3(CC / 128, NROW / 64), 256, G64_SMEM>>>(
        (const __half*)p_ao, (const __half*)p_wpt, bproj, out_main);
}

// round 15
// speedup vs baseline: 1.1108x; 1.1108x over previous
#include <cuda_runtime.h>
#include <cuda_fp16.h>
#include <math.h>
#include <stdint.h>

// Problem constants
#define BB    2
#define TT    2048
#define CC    512
#define HH    8
#define DD    64
#define C3    1536
#define KSEL  4
#define GAMMA_F 2.5f
#define RHO_F   0.085f
#define TAUCLIP 5.0f
#define NROW  (BB*TT)       // 4096
#define KTOT  512

typedef unsigned long long ull;

// ---------------- scratch (device globals) ---------------------------------
__device__ float g_qkv[(size_t)NROW * C3];        // 24 MB fp32
// fp16 operands
__device__ __half g_x_h[(size_t)NROW * KTOT];     // x (fp16)
__device__ __half g_wqt[(size_t)C3 * KTOT];       // Wqkv^T fp16
__device__ __half g_wpt[(size_t)CC * KTOT];       // Wproj^T fp16
__device__ __half g_ao[(size_t)NROW * KTOT];      // attn_out fp16

// ===================== helpers ==============================================
__device__ __forceinline__ uint32_t smem_u32(const void* p) {
    uint32_t a;
    asm("{ .reg .u64 t; cvta.to.shared.u64 t, %1; cvt.u32.u64 %0, t; }" : "=r"(a) : "l"(p));
    return a;
}
__device__ __forceinline__ void ldsm_x4(uint32_t& r0, uint32_t& r1, uint32_t& r2, uint32_t& r3,
                                        uint32_t addr) {
    asm volatile("ldmatrix.sync.aligned.m8n8.x4.shared.b16 {%0,%1,%2,%3}, [%4];"
                 : "=r"(r0), "=r"(r1), "=r"(r2), "=r"(r3) : "r"(addr));
}
__device__ __forceinline__ void mma_fp16(float* d, const uint32_t* a, uint32_t b0, uint32_t b1) {
    asm("mma.sync.aligned.m16n8k16.row.col.f32.f16.f16.f32 "
        "{%0,%1,%2,%3}, {%4,%5,%6,%7}, {%8,%9}, {%0,%1,%2,%3};"
        : "+f"(d[0]), "+f"(d[1]), "+f"(d[2]), "+f"(d[3])
        : "r"(a[0]), "r"(a[1]), "r"(a[2]), "r"(a[3]), "r"(b0), "r"(b1));
}

// ===================== operand prep (vectorized) ============================
__global__ void convert_h(const float* __restrict__ in,
                          __half* __restrict__ hi, int n4) {
    int i = blockIdx.x * 256 + threadIdx.x;     // float4 index
    if (i < n4) {
        float4 v = reinterpret_cast<const float4*>(in)[i];
        reinterpret_cast<__half2*>(hi)[i * 2]     = __floats2half2_rn(v.x, v.y);
        reinterpret_cast<__half2*>(hi)[i * 2 + 1] = __floats2half2_rn(v.z, v.w);
    }
}

// W [K,N] fp32 -> [N,K] fp16
__global__ void transpose_half(const float* __restrict__ W,
                               __half* __restrict__ out, int K, int N) {
    __shared__ float tile[32][33];
    int n0 = blockIdx.x * 32, k0 = blockIdx.y * 32;
    int tx = threadIdx.x, ty = threadIdx.y;
    #pragma unroll
    for (int i = 0; i < 32; i += 8)
        tile[ty + i][tx] = W[(size_t)(k0 + ty + i) * N + n0 + tx];
    __syncthreads();
    #pragma unroll
    for (int i = 0; i < 32; i += 8)
        out[(size_t)(n0 + ty + i) * K + k0 + tx] = __float2half(tile[tx][ty + i]);
}

// ===================== K64 / 2-stage / swizzled GEMM core (BM=64) ===========
// BM=64, BN=128, 8 warps (4m x 2n), warp tile 16x64.  Tiles: rows x 128B,
// XOR swizzle: unit' = unit ^ (row & 7).  occ 3 target.
#define A64_TILE 8192                // 64 rows x 128 B
#define B64_TILE 16384               // 128 rows x 128 B
#define G64_STAGE (A64_TILE + B64_TILE)       // A, B = 24576
#define G64_SMEM (2 * G64_STAGE)     // 49152
#define G64_NCH 8                    // 512 / 64

__device__ __forceinline__ void g64_load(
    uint32_t sm_base, int stage, int c, int m0, int n0, int tid,
    const __half* __restrict__ Ah, const __half* __restrict__ Bh)
{
    if (c < G64_NCH) {
        uint32_t sbase = sm_base + stage * G64_STAGE;
        const int k0 = c * 64;
        #pragma unroll
        for (int i = 0; i < 2; i++) {            // A: 64 rows x 8 units
            int u = tid + i * 256;
            int r = u >> 3, cu = u & 7;
            const void* gp = Ah + (size_t)(m0 + r) * KTOT + k0 + cu * 8;
            uint32_t dst = sbase + r * 128 + ((cu ^ (r & 7)) << 4);
            asm volatile("cp.async.cg.shared.global [%0], [%1], 16;" :: "r"(dst), "l"(gp));
        }
        #pragma unroll
        for (int i = 0; i < 4; i++) {            // B: 128 rows x 8 units
            int u = tid + i * 256;
            int r = u >> 3, cu = u & 7;
            const void* gp = Bh + (size_t)(n0 + r) * KTOT + k0 + cu * 8;
            uint32_t dst = sbase + A64_TILE + r * 128 + ((cu ^ (r & 7)) << 4);
            asm volatile("cp.async.cg.shared.global [%0], [%1], 16;" :: "r"(dst), "l"(gp));
        }
    }
    asm volatile("cp.async.commit_group;" ::: "memory");
}

__device__ __forceinline__ void gemm64_body(
    uint32_t sm_base, int m0, int n0, int tid,
    const __half* __restrict__ Ah, const __half* __restrict__ Bh,
    const float* __restrict__ bias, float* __restrict__ Cout, int N_out)
{
    const int wid = tid >> 5, lane = tid & 31;
    const int wm = wid >> 1, wn = wid & 1;       // 4m x 2n, warp tile 16x64

    float acc[8][4];
    #pragma unroll
    for (int j = 0; j < 8; j++)
        #pragma unroll
        for (int l = 0; l < 4; l++) acc[j][l] = 0.f;

    g64_load(sm_base, 0, 0, m0, n0, tid, Ah, Bh);
    g64_load(sm_base, 1, 1, m0, n0, tid, Ah, Bh);

    const int lrow = lane & 15;
    const int lu8 = (lane >> 4);

    for (int c = 0; c < G64_NCH; c++) {
        asm volatile("cp.async.wait_group 1;" ::: "memory");
        __syncthreads();
        const uint32_t stg = sm_base + (c & 1) * G64_STAGE;

        #pragma unroll
        for (int kk = 0; kk < 4; kk++) {
            const int ubase = kk * 2 + lu8;
            uint32_t ah[4], bh[4][4];
            {
                int r = wm * 16 + lrow;
                uint32_t ra = stg + r * 128 + ((ubase ^ (r & 7)) << 4);
                ldsm_x4(ah[0], ah[1], ah[2], ah[3], ra);
            }
            #pragma unroll
            for (int jn = 0; jn < 4; jn++) {
                int r = wn * 64 + jn * 16 + lrow;
                uint32_t rb = stg + A64_TILE + r * 128 + ((ubase ^ (r & 7)) << 4);
                ldsm_x4(bh[jn][0], bh[jn][1], bh[jn][2], bh[jn][3], rb);
            }
            #pragma unroll
            for (int jn = 0; jn < 4; jn++) {
                mma_fp16(acc[jn * 2],     ah, bh[jn][0], bh[jn][2]);
                mma_fp16(acc[jn * 2 + 1], ah, bh[jn][1], bh[jn][3]);
            }
        }
        __syncthreads();
        g64_load(sm_base, c & 1, c + 2, m0, n0, tid, Ah, Bh);
    }

    {
        int rbase = m0 + wm * 16 + (lane >> 2);
        #pragma unroll
        for (int jf = 0; jf < 8; jf++) {
            int col = n0 + wn * 64 + jf * 8 + (lane & 3) * 2;
            float2 b2 = *reinterpret_cast<const float2*>(bias + col);
            float2 o0, o1;
            o0.x = acc[jf][0] + b2.x; o0.y = acc[jf][1] + b2.y;
            o1.x = acc[jf][2] + b2.x; o1.y = acc[jf][3] + b2.y;
            *reinterpret_cast<float2*>(Cout + (size_t)rbase * N_out + col) = o0;
            *reinterpret_cast<float2*>(Cout + (size_t)(rbase + 8) * N_out + col) = o1;
        }
    }
}

// QKV: single fp16.
__global__ __launch_bounds__(256, 3) void qkv_gemm64(
    const __half* __restrict__ Ah, const __half* __restrict__ Bh,
    const float* __restrict__ bias, float* __restrict__ Cout)
{
    extern __shared__ char smem[];
    const uint32_t sm_base = smem_u32(smem);
    gemm64_body(sm_base, blockIdx.y * 64, blockIdx.x * 128, threadIdx.x,
                Ah, Bh, bias, Cout, C3);
}

// proj: single fp16.
__global__ __launch_bounds__(256, 3) void proj_gemm64(
    const __half* __restrict__ Ah, const __half* __restrict__ Bh,
    const float* __restrict__ bias, float* __restrict__ Cout)
{
    extern __shared__ char smem[];
    const uint32_t sm_base = smem_u32(smem);
    gemm64_body(sm_base, blockIdx.y * 64, blockIdx.x * 128, threadIdx.x,
                Ah, Bh, bias, Cout, CC);
}

// ===================== fused topk + attention + tau_new =====================
// 256 threads/row (R13-proven structure): 2 float4/thread, 8-warp tournament
// topk, warp==head attention, single fp16 ao output.
__global__ __launch_bounds__(256) void attn_topk_fused(const float* __restrict__ tau,
                                                       float* __restrict__ out_tau) {
    const int row = blockIdx.x;
    const int tid = threadIdx.x;
    const int warp = tid >> 5, lane = tid & 31;   // warp == head
    const int b = row / TT;

    __shared__ ull   swk[8 * 4];                  // per-warp top4
    __shared__ float sred[8];
    __shared__ float srowsum;
    __shared__ int   sidx[KSEL];
    __shared__ float sbias[KSEL];
    __shared__ float stval[KSEL];
    __shared__ float ssig[KSEL];
    __shared__ float sinv;

    // ---- load tau row into REGISTERS + per-thread top4 + sum ----
    const float4* tin = reinterpret_cast<const float4*>(tau + (size_t)row * TT);
    float4 v0 = tin[tid];
    float4 v1 = tin[tid + 256];
    float sum = (v0.x + v0.y) + (v0.z + v0.w) + (v1.x + v1.y) + (v1.z + v1.w);

    ull k0 = 0, k1 = 0, k2 = 0, k3 = 0;
    #define TK_INS(val, col) do { \
        ull key = ((ull)__float_as_uint(val) << 32) | (unsigned)(0x7FFFFFFF - (col)); \
        if (key > k3) { \
            if (key > k0)      { k3 = k2; k2 = k1; k1 = k0; k0 = key; } \
            else if (key > k1) { k3 = k2; k2 = k1; k1 = key; } \
            else if (key > k2) { k3 = k2; k2 = key; } \
            else               { k3 = key; } \
        } } while (0)
    {
        int c0 = tid * 4, c1 = (tid + 256) * 4;
        TK_INS(v0.x, c0);     TK_INS(v0.y, c0 + 1);
        TK_INS(v0.z, c0 + 2); TK_INS(v0.w, c0 + 3);
        TK_INS(v1.x, c1);     TK_INS(v1.y, c1 + 1);
        TK_INS(v1.z, c1 + 2); TK_INS(v1.w, c1 + 3);
    }
    #undef TK_INS

    // ---- warp top-4: 4-round argmax tournament (keys unique) ----
    ull t0, t1, t2, t3;
    {
        ull h = k0;
        #pragma unroll
        for (int r = 0; r < 4; r++) {
            ull m = h;
            #pragma unroll
            for (int o = 16; o > 0; o >>= 1) {
                ull bb = __shfl_xor_sync(0xffffffffu, m, o);
                if (bb > m) m = bb;
            }
            if (r == 0) t0 = m; else if (r == 1) t1 = m;
            else if (r == 2) t2 = m; else t3 = m;
            if (h == m) { h = k1; k1 = k2; k2 = k3; k3 = 0; }  // unique winner pops
        }
    }
    #pragma unroll
    for (int o = 16; o > 0; o >>= 1) sum += __shfl_xor_sync(0xffffffffu, sum, o);

    if (lane == 0) {
        swk[warp * 4 + 0] = t0; swk[warp * 4 + 1] = t1;
        swk[warp * 4 + 2] = t2; swk[warp * 4 + 3] = t3;
        sred[warp] = sum;
    }
    __syncthreads();

    // ---- warp 0: tournament over the 8 per-warp lists (replicated x4) ----
    if (warp == 0) {
        int src = lane & 7;
        ull l0 = swk[src * 4], l1 = swk[src * 4 + 1];
        ull l2 = swk[src * 4 + 2], l3 = swk[src * 4 + 3];
        ull m0, m1, m2, m3;
        {
            ull h = l0;
            #pragma unroll
            for (int r = 0; r < 4; r++) {
                ull m = h;
                #pragma unroll
                for (int o = 4; o > 0; o >>= 1) {       // within replicated 8-group
                    ull bb = __shfl_xor_sync(0xffffffffu, m, o);
                    if (bb > m) m = bb;
                }
                if (r == 0) m0 = m; else if (r == 1) m1 = m;
                else if (r == 2) m2 = m; else m3 = m;
                if (h == m) { h = l1; l1 = l2; l2 = l3; l3 = 0; }
            }
        }
        float rs = sred[src];
        rs += __shfl_xor_sync(0xffffffffu, rs, 1);
        rs += __shfl_xor_sync(0xffffffffu, rs, 2);
        rs += __shfl_xor_sync(0xffffffffu, rs, 4);
        if (lane < KSEL) {
            ull key = (lane == 0) ? m0 : (lane == 1) ? m1 : (lane == 2) ? m2 : m3;
            int id = 0x7FFFFFFF - (int)(key & 0xFFFFFFFFu);
            float tv = __uint_as_float((unsigned)(key >> 32));
            sidx[lane]  = id;
            stval[lane] = tv;
            sbias[lane] = GAMMA_F * logf(tv + 1e-8f);
            ssig[lane]  = 0.f;
        }
        if (lane == 0) srowsum = rs;
    }
    __syncthreads();

    // ---- sparse attention ----
    const float* qp = g_qkv + (size_t)row * C3 + warp * DD;
    const float q0 = qp[lane], q1 = qp[lane + 32];

    float logit[KSEL];
    #pragma unroll
    for (int j = 0; j < KSEL; j++) {
        int s = sidx[j];
        const float* kp = g_qkv + (size_t)(b * TT + s) * C3 + CC + warp * DD;
        float p = q0 * kp[lane] + q1 * kp[lane + 32];
        #pragma unroll
        for (int o = 16; o > 0; o >>= 1) p += __shfl_xor_sync(0xffffffffu, p, o);
        logit[j] = p * 0.125f + sbias[j];
    }
    float m = fmaxf(fmaxf(logit[0], logit[1]), fmaxf(logit[2], logit[3]));
    float e[KSEL], se = 0.f;
    #pragma unroll
    for (int j = 0; j < KSEL; j++) { e[j] = expf(logit[j] - m); se += e[j]; }
    float inv = 1.f / se;
    float w[KSEL];
    #pragma unroll
    for (int j = 0; j < KSEL; j++) w[j] = e[j] * inv;

    float o0 = 0.f, o1 = 0.f;
    #pragma unroll
    for (int j = 0; j < KSEL; j++) {
        const float* vp = g_qkv + (size_t)(b * TT + sidx[j]) * C3 + 2 * CC + warp * DD;
        o0 = fmaf(w[j], vp[lane], o0);
        o1 = fmaf(w[j], vp[lane + 32], o1);
    }
    size_t obase = (size_t)row * KTOT + warp * DD;
    g_ao[obase + lane]      = __float2half(o0);
    g_ao[obase + lane + 32] = __float2half(o1);

    if (lane == 0) {
        #pragma unroll
        for (int j = 0; j < KSEL; j++) atomicAdd(&ssig[j], w[j] * (1.0f / HH));
    }
    __syncthreads();
    if (tid == 0) {
        float rs = srowsum * (1.0f - RHO_F);
        #pragma unroll
        for (int j = 0; j < KSEL; j++) { float s = ssig[j]; rs += s * s * s; }
        sinv = 1.f / (rs + 1e-8f);
    }
    __syncthreads();

    // ---- tau_new: scale from registers + patch ----
    const float f = (1.0f - RHO_F) * sinv;
    float4* tout = reinterpret_cast<float4*>(out_tau + (size_t)row * TT);
    float4 w0, w1;
    w0.x = fminf(v0.x * f, TAUCLIP); w0.y = fminf(v0.y * f, TAUCLIP);
    w0.z = fminf(v0.z * f, TAUCLIP); w0.w = fminf(v0.w * f, TAUCLIP);
    w1.x = fminf(v1.x * f, TAUCLIP); w1.y = fminf(v1.y * f, TAUCLIP);
    w1.z = fminf(v1.z * f, TAUCLIP); w1.w = fminf(v1.w * f, TAUCLIP);
    tout[tid] = w0;
    tout[tid + 256] = w1;
    __syncthreads();
    if (tid < KSEL) {
        float s = ssig[tid];
        float vv = stval[tid] * (1.0f - RHO_F) + s * s * s;
        out_tau[(size_t)row * TT + sidx[tid]] = fminf(vv * sinv, TAUCLIP);
    }
}

// ===================== launch ===============================================
extern "C" void kernel_launch(void* const* d_in, const int* in_sizes, int n_in,
                              void* d_out, int out_size) {
    const float* x     = (const float*)d_in[0];
    const float* tau   = (const float*)d_in[1];
    const float* Wqkv  = (const float*)d_in[2];
    const float* bqkv  = (const float*)d_in[3];
    const float* Wproj = (const float*)d_in[4];
    const float* bproj = (const float*)d_in[5];

    float* out_main = (float*)d_out;
    float* out_tau  = out_main + (size_t)NROW * CC;

    void *p_qkv, *p_xh, *p_wqt, *p_wpt, *p_ao;
    cudaGetSymbolAddress(&p_qkv, g_qkv);
    cudaGetSymbolAddress(&p_xh, g_x_h);
    cudaGetSymbolAddress(&p_wqt, g_wqt);  cudaGetSymbolAddress(&p_wpt, g_wpt);
    cudaGetSymbolAddress(&p_ao, g_ao);

    cudaFuncSetAttribute(qkv_gemm64, cudaFuncAttributeMaxDynamicSharedMemorySize, G64_SMEM);
    cudaFuncSetAttribute(proj_gemm64, cudaFuncAttributeMaxDynamicSharedMemorySize, G64_SMEM);

    // 1-2. prep needed for QKV
    convert_h<<<(NROW * KTOT / 4) / 256, 256>>>(x, (__half*)p_xh, NROW * KTOT / 4);
    transpose_half<<<dim3(C3 / 32, KTOT / 32), dim3(32, 8)>>>(Wqkv, (__half*)p_wqt, KTOT, C3);

    // 3. QKV GEMM (single fp16, BM=64, occ 3): 768 CTAs
    qkv_gemm64<<<dim3(12, NROW / 64), 256, G64_SMEM>>>(
        (const __half*)p_xh, (const __half*)p_wqt, bqkv, (float*)p_qkv);

    // 4. fused: topk + sparse attention + tau_new (256 thr)  (launch #4 -> profiled)
    attn_topk_fused<<<NROW, 256>>>(tau, out_tau);

    // 5. Wproj transpose
    transpose_half<<<dim3(CC / 32, KTOT / 32), dim3(32, 8)>>>(Wproj, (__half*)p_wpt, KTOT, CC);

    // 6. proj GEMM (single fp16, BM=64): 256 CTAs, single wave
    proj_gemm64<<<dim3(CC / 128, NROW / 64), 256, G64_SMEM>>>(
        (const __half*)p_ao, (const __half*)p_wpt, bproj, out_main);
}

// round 16
// speedup vs baseline: 1.2623x; 1.1364x over previous
#include <cuda_runtime.h>
#include <cuda_fp16.h>
#include <math.h>
#include <stdint.h>

// Problem constants
#define BB    2
#define TT    2048
#define CC    512
#define HH    8
#define DD    64
#define C3    1536
#define KSEL  4
#define GAMMA_F 2.5f
#define RHO_F   0.085f
#define TAUCLIP 5.0f
#define NROW  (BB*TT)       // 4096
#define KTOT  512

typedef unsigned long long ull;

// ---------------- scratch (device globals) ---------------------------------
__device__ float g_qkv[(size_t)NROW * C3];        // 24 MB fp32
__device__ __half g_x_h[(size_t)NROW * KTOT];     // x (fp16)
__device__ __half g_wqt[(size_t)C3 * KTOT];       // Wqkv^T fp16
__device__ __half g_wpt[(size_t)CC * KTOT];       // Wproj^T fp16
__device__ __half g_ao[(size_t)NROW * KTOT];      // attn_out fp16

// ===================== helpers ==============================================
__device__ __forceinline__ uint32_t smem_u32(const void* p) {
    uint32_t a;
    asm("{ .reg .u64 t; cvta.to.shared.u64 t, %1; cvt.u32.u64 %0, t; }" : "=r"(a) : "l"(p));
    return a;
}
__device__ __forceinline__ void ldsm_x4(uint32_t& r0, uint32_t& r1, uint32_t& r2, uint32_t& r3,
                                        uint32_t addr) {
    asm volatile("ldmatrix.sync.aligned.m8n8.x4.shared.b16 {%0,%1,%2,%3}, [%4];"
                 : "=r"(r0), "=r"(r1), "=r"(r2), "=r"(r3) : "r"(addr));
}
__device__ __forceinline__ void mma_fp16(float* d, const uint32_t* a, uint32_t b0, uint32_t b1) {
    asm("mma.sync.aligned.m16n8k16.row.col.f32.f16.f16.f32 "
        "{%0,%1,%2,%3}, {%4,%5,%6,%7}, {%8,%9}, {%0,%1,%2,%3};"
        : "+f"(d[0]), "+f"(d[1]), "+f"(d[2]), "+f"(d[3])
        : "r"(a[0]), "r"(a[1]), "r"(a[2]), "r"(a[3]), "r"(b0), "r"(b1));
}
// Full-warp 64-bit key max via two u32 REDUX ops (exact, same order as u64 max)
__device__ __forceinline__ ull warp_max_key(ull h) {
    unsigned hi = (unsigned)(h >> 32);
    unsigned mhi = __reduce_max_sync(0xffffffffu, hi);
    unsigned lo = (hi == mhi) ? (unsigned)h : 0u;
    unsigned mlo = __reduce_max_sync(0xffffffffu, lo);
    return ((ull)mhi << 32) | mlo;
}

// ===================== fused operand prep ===================================
// blocks [0,2048): convert x -> fp16 (float4-wise)
// blocks [2048,2816): transpose Wqkv (48 x 16 tiles of 32x32)
// blocks [2816,3072): transpose Wproj (16 x 16 tiles)
__device__ __forceinline__ void transp_tile(const float* __restrict__ W,
                                            __half* __restrict__ out,
                                            int n0, int k0, int N, int tid) {
    __shared__ float tile[32][33];
    int tx = tid & 31, ty = tid >> 5;            // 32 x 8
    #pragma unroll
    for (int i = 0; i < 32; i += 8)
        tile[ty + i][tx] = W[(size_t)(k0 + ty + i) * N + n0 + tx];
    __syncthreads();
    #pragma unroll
    for (int i = 0; i < 32; i += 8)
        out[(size_t)(n0 + ty + i) * KTOT + k0 + tx] = __float2half(tile[tx][ty + i]);
}

__global__ void prep_fused(const float* __restrict__ x, __half* __restrict__ xh,
                           const float* __restrict__ Wq, __half* __restrict__ wqt,
                           const float* __restrict__ Wp, __half* __restrict__ wpt) {
    const int bid = blockIdx.x;
    const int tid = threadIdx.x;
    if (bid < 2048) {
        int i = bid * 256 + tid;                 // float4 index, n4 = 524288
        float4 v = reinterpret_cast<const float4*>(x)[i];
        reinterpret_cast<__half2*>(xh)[i * 2]     = __floats2half2_rn(v.x, v.y);
        reinterpret_cast<__half2*>(xh)[i * 2 + 1] = __floats2half2_rn(v.z, v.w);
    } else if (bid < 2048 + 768) {
        int t = bid - 2048;                      // Wqkv: N=C3, 48 n-tiles x 16 k-tiles
        transp_tile(Wq, wqt, (t % 48) * 32, (t / 48) * 32, C3, tid);
    } else {
        int t = bid - 2816;                      // Wproj: N=CC, 16 x 16
        transp_tile(Wp, wpt, (t % 16) * 32, (t / 16) * 32, CC, tid);
    }
}

// ===================== K64 / 2-stage / swizzled GEMM core (BM=64) ===========
#define A64_TILE 8192                // 64 rows x 128 B
#define B64_TILE 16384               // 128 rows x 128 B
#define G64_STAGE (A64_TILE + B64_TILE)       // 24576
#define G64_SMEM (2 * G64_STAGE)     // 49152
#define G64_NCH 8                    // 512 / 64

__device__ __forceinline__ void g64_load(
    uint32_t sm_base, int stage, int c, int m0, int n0, int tid,
    const __half* __restrict__ Ah, const __half* __restrict__ Bh)
{
    if (c < G64_NCH) {
        uint32_t sbase = sm_base + stage * G64_STAGE;
        const int k0 = c * 64;
        #pragma unroll
        for (int i = 0; i < 2; i++) {            // A: 64 rows x 8 units
            int u = tid + i * 256;
            int r = u >> 3, cu = u & 7;
            const void* gp = Ah + (size_t)(m0 + r) * KTOT + k0 + cu * 8;
            uint32_t dst = sbase + r * 128 + ((cu ^ (r & 7)) << 4);
            asm volatile("cp.async.cg.shared.global [%0], [%1], 16;" :: "r"(dst), "l"(gp));
        }
        #pragma unroll
        for (int i = 0; i < 4; i++) {            // B: 128 rows x 8 units
            int u = tid + i * 256;
            int r = u >> 3, cu = u & 7;
            const void* gp = Bh + (size_t)(n0 + r) * KTOT + k0 + cu * 8;
            uint32_t dst = sbase + A64_TILE + r * 128 + ((cu ^ (r & 7)) << 4);
            asm volatile("cp.async.cg.shared.global [%0], [%1], 16;" :: "r"(dst), "l"(gp));
        }
    }
    asm volatile("cp.async.commit_group;" ::: "memory");
}

__device__ __forceinline__ void gemm64_body(
    uint32_t sm_base, int m0, int n0, int tid,
    const __half* __restrict__ Ah, const __half* __restrict__ Bh,
    const float* __restrict__ bias, float* __restrict__ Cout, int N_out)
{
    const int wid = tid >> 5, lane = tid & 31;
    const int wm = wid >> 1, wn = wid & 1;       // 4m x 2n, warp tile 16x64

    float acc[8][4];
    #pragma unroll
    for (int j = 0; j < 8; j++)
        #pragma unroll
        for (int l = 0; l < 4; l++) acc[j][l] = 0.f;

    g64_load(sm_base, 0, 0, m0, n0, tid, Ah, Bh);
    g64_load(sm_base, 1, 1, m0, n0, tid, Ah, Bh);

    const int lrow = lane & 15;
    const int lu8 = (lane >> 4);

    for (int c = 0; c < G64_NCH; c++) {
        asm volatile("cp.async.wait_group 1;" ::: "memory");
        __syncthreads();
        const uint32_t stg = sm_base + (c & 1) * G64_STAGE;

        #pragma unroll
        for (int kk = 0; kk < 4; kk++) {
            const int ubase = kk * 2 + lu8;
            uint32_t ah[4], bh[4][4];
            {
                int r = wm * 16 + lrow;
                uint32_t ra = stg + r * 128 + ((ubase ^ (r & 7)) << 4);
                ldsm_x4(ah[0], ah[1], ah[2], ah[3], ra);
            }
            #pragma unroll
            for (int jn = 0; jn < 4; jn++) {
                int r = wn * 64 + jn * 16 + lrow;
                uint32_t rb = stg + A64_TILE + r * 128 + ((ubase ^ (r & 7)) << 4);
                ldsm_x4(bh[jn][0], bh[jn][1], bh[jn][2], bh[jn][3], rb);
            }
            #pragma unroll
            for (int jn = 0; jn < 4; jn++) {
                mma_fp16(acc[jn * 2],     ah, bh[jn][0], bh[jn][2]);
                mma_fp16(acc[jn * 2 + 1], ah, bh[jn][1], bh[jn][3]);
            }
        }
        __syncthreads();
        g64_load(sm_base, c & 1, c + 2, m0, n0, tid, Ah, Bh);
    }

    {
        int rbase = m0 + wm * 16 + (lane >> 2);
        #pragma unroll
        for (int jf = 0; jf < 8; jf++) {
            int col = n0 + wn * 64 + jf * 8 + (lane & 3) * 2;
            float2 b2 = *reinterpret_cast<const float2*>(bias + col);
            float2 o0, o1;
            o0.x = acc[jf][0] + b2.x; o0.y = acc[jf][1] + b2.y;
            o1.x = acc[jf][2] + b2.x; o1.y = acc[jf][3] + b2.y;
            *reinterpret_cast<float2*>(Cout + (size_t)rbase * N_out + col) = o0;
            *reinterpret_cast<float2*>(Cout + (size_t)(rbase + 8) * N_out + col) = o1;
        }
    }
}

__global__ __launch_bounds__(256, 3) void qkv_gemm64(
    const __half* __restrict__ Ah, const __half* __restrict__ Bh,
    const float* __restrict__ bias, float* __restrict__ Cout)
{
    extern __shared__ char smem[];
    gemm64_body(smem_u32(smem), blockIdx.y * 64, blockIdx.x * 128, threadIdx.x,
                Ah, Bh, bias, Cout, C3);
}

__global__ __launch_bounds__(256, 3) void proj_gemm64(
    const __half* __restrict__ Ah, const __half* __restrict__ Bh,
    const float* __restrict__ bias, float* __restrict__ Cout)
{
    extern __shared__ char smem[];
    gemm64_body(smem_u32(smem), blockIdx.y * 64, blockIdx.x * 128, threadIdx.x,
                Ah, Bh, bias, Cout, CC);
}

// ===================== fused topk + attention + tau_new =====================
// 256 threads/row; REDUX-based tournament topk (bit-exact vs u64 max).
__global__ __launch_bounds__(256) void attn_topk_fused(const float* __restrict__ tau,
                                                       float* __restrict__ out_tau) {
    const int row = blockIdx.x;
    const int tid = threadIdx.x;
    const int warp = tid >> 5, lane = tid & 31;   // warp == head
    const int b = row / TT;

    __shared__ ull   swk[8 * 4];                  // per-warp top4
    __shared__ float sred[8];
    __shared__ float srowsum;
    __shared__ int   sidx[KSEL];
    __shared__ float sbias[KSEL];
    __shared__ float stval[KSEL];
    __shared__ float ssig[KSEL];
    __shared__ float sinv;

    // ---- load tau row into REGISTERS + per-thread top4 + sum ----
    const float4* tin = reinterpret_cast<const float4*>(tau + (size_t)row * TT);
    float4 v0 = tin[tid];
    float4 v1 = tin[tid + 256];
    float sum = (v0.x + v0.y) + (v0.z + v0.w) + (v1.x + v1.y) + (v1.z + v1.w);

    ull k0 = 0, k1 = 0, k2 = 0, k3 = 0;
    #define TK_INS(val, col) do { \
        ull key = ((ull)__float_as_uint(val) << 32) | (unsigned)(0x7FFFFFFF - (col)); \
        if (key > k3) { \
            if (key > k0)      { k3 = k2; k2 = k1; k1 = k0; k0 = key; } \
            else if (key > k1) { k3 = k2; k2 = k1; k1 = key; } \
            else if (key > k2) { k3 = k2; k2 = key; } \
            else               { k3 = key; } \
        } } while (0)
    {
        int c0 = tid * 4, c1 = (tid + 256) * 4;
        TK_INS(v0.x, c0);     TK_INS(v0.y, c0 + 1);
        TK_INS(v0.z, c0 + 2); TK_INS(v0.w, c0 + 3);
        TK_INS(v1.x, c1);     TK_INS(v1.y, c1 + 1);
        TK_INS(v1.z, c1 + 2); TK_INS(v1.w, c1 + 3);
    }
    #undef TK_INS

    // ---- warp top-4: 4-round REDUX tournament (keys unique) ----
    ull t0, t1, t2, t3;
    {
        ull h = k0;
        #pragma unroll
        for (int r = 0; r < 4; r++) {
            ull m = warp_max_key(h);
            if (r == 0) t0 = m; else if (r == 1) t1 = m;
            else if (r == 2) t2 = m; else t3 = m;
            if (h == m) { h = k1; k1 = k2; k2 = k3; k3 = 0; }  // unique winner pops
        }
    }
    #pragma unroll
    for (int o = 16; o > 0; o >>= 1) sum += __shfl_xor_sync(0xffffffffu, sum, o);

    if (lane == 0) {
        swk[warp * 4 + 0] = t0; swk[warp * 4 + 1] = t1;
        swk[warp * 4 + 2] = t2; swk[warp * 4 + 3] = t3;
        sred[warp] = sum;
    }
    __syncthreads();

    // ---- warp 0: REDUX tournament over 8 lists replicated x4 (full-warp) ----
    if (warp == 0) {
        int src = lane & 7;
        ull l0 = swk[src * 4], l1 = swk[src * 4 + 1];
        ull l2 = swk[src * 4 + 2], l3 = swk[src * 4 + 3];
        ull m0, m1, m2, m3;
        {
            ull h = l0;
            #pragma unroll
            for (int r = 0; r < 4; r++) {
                ull m = warp_max_key(h);     // replication x4 -> global max over 8 lists
                if (r == 0) m0 = m; else if (r == 1) m1 = m;
                else if (r == 2) m2 = m; else m3 = m;
                if (h == m) { h = l1; l1 = l2; l2 = l3; l3 = 0; }
            }
        }
        float rs = sred[src];
        rs += __shfl_xor_sync(0xffffffffu, rs, 1);
        rs += __shfl_xor_sync(0xffffffffu, rs, 2);
        rs += __shfl_xor_sync(0xffffffffu, rs, 4);
        if (lane < KSEL) {
            ull key = (lane == 0) ? m0 : (lane == 1) ? m1 : (lane == 2) ? m2 : m3;
            int id = 0x7FFFFFFF - (int)(key & 0xFFFFFFFFu);
            float tv = __uint_as_float((unsigned)(key >> 32));
            sidx[lane]  = id;
            stval[lane] = tv;
            sbias[lane] = GAMMA_F * logf(tv + 1e-8f);
            ssig[lane]  = 0.f;
        }
        if (lane == 0) srowsum = rs;
    }
    __syncthreads();

    // ---- sparse attention ----
    const float* qp = g_qkv + (size_t)row * C3 + warp * DD;
    const float q0 = qp[lane], q1 = qp[lane + 32];

    float logit[KSEL];
    #pragma unroll
    for (int j = 0; j < KSEL; j++) {
        int s = sidx[j];
        const float* kp = g_qkv + (size_t)(b * TT + s) * C3 + CC + warp * DD;
        float p = q0 * kp[lane] + q1 * kp[lane + 32];
        #pragma unroll
        for (int o = 16; o > 0; o >>= 1) p += __shfl_xor_sync(0xffffffffu, p, o);
        logit[j] = p * 0.125f + sbias[j];
    }
    float m = fmaxf(fmaxf(logit[0], logit[1]), fmaxf(logit[2], logit[3]));
    float e[KSEL], se = 0.f;
    #pragma unroll
    for (int j = 0; j < KSEL; j++) { e[j] = expf(logit[j] - m); se += e[j]; }
    float inv = 1.f / se;
    float w[KSEL];
    #pragma unroll
    for (int j = 0; j < KSEL; j++) w[j] = e[j] * inv;

    float o0 = 0.f, o1 = 0.f;
    #pragma unroll
    for (int j = 0; j < KSEL; j++) {
        const float* vp = g_qkv + (size_t)(b * TT + sidx[j]) * C3 + 2 * CC + warp * DD;
        o0 = fmaf(w[j], vp[lane], o0);
        o1 = fmaf(w[j], vp[lane + 32], o1);
    }
    size_t obase = (size_t)row * KTOT + warp * DD;
    g_ao[obase + lane]      = __float2half(o0);
    g_ao[obase + lane + 32] = __float2half(o1);

    if (lane == 0) {
        #pragma unroll
        for (int j = 0; j < KSEL; j++) atomicAdd(&ssig[j], w[j] * (1.0f / HH));
    }
    __syncthreads();
    if (tid == 0) {
        float rs = srowsum * (1.0f - RHO_F);
        #pragma unroll
        for (int j = 0; j < KSEL; j++) { float s = ssig[j]; rs += s * s * s; }
        sinv = 1.f / (rs + 1e-8f);
    }
    __syncthreads();

    // ---- tau_new: scale from registers + patch ----
    const float f = (1.0f - RHO_F) * sinv;
    float4* tout = reinterpret_cast<float4*>(out_tau + (size_t)row * TT);
    float4 w0, w1;
    w0.x = fminf(v0.x * f, TAUCLIP); w0.y = fminf(v0.y * f, TAUCLIP);
    w0.z = fminf(v0.z * f, TAUCLIP); w0.w = fminf(v0.w * f, TAUCLIP);
    w1.x = fminf(v1.x * f, TAUCLIP); w1.y = fminf(v1.y * f, TAUCLIP);
    w1.z = fminf(v1.z * f, TAUCLIP); w1.w = fminf(v1.w * f, TAUCLIP);
    tout[tid] = w0;
    tout[tid + 256] = w1;
    __syncthreads();
    if (tid < KSEL) {
        float s = ssig[tid];
        float vv = stval[tid] * (1.0f - RHO_F) + s * s * s;
        out_tau[(size_t)row * TT + sidx[tid]] = fminf(vv * sinv, TAUCLIP);
    }
}

// ===================== launch ===============================================
extern "C" void kernel_launch(void* const* d_in, const int* in_sizes, int n_in,
                              void* d_out, int out_size) {
    const float* x     = (const float*)d_in[0];
    const float* tau   = (const float*)d_in[1];
    const float* Wqkv  = (const float*)d_in[2];
    const float* bqkv  = (const float*)d_in[3];
    const float* Wproj = (const float*)d_in[4];
    const float* bproj = (const float*)d_in[5];

    float* out_main = (float*)d_out;
    float* out_tau  = out_main + (size_t)NROW * CC;

    void *p_qkv, *p_xh, *p_wqt, *p_wpt, *p_ao;
    cudaGetSymbolAddress(&p_qkv, g_qkv);
    cudaGetSymbolAddress(&p_xh, g_x_h);
    cudaGetSymbolAddress(&p_wqt, g_wqt);  cudaGetSymbolAddress(&p_wpt, g_wpt);
    cudaGetSymbolAddress(&p_ao, g_ao);

    cudaFuncSetAttribute(qkv_gemm64, cudaFuncAttributeMaxDynamicSharedMemorySize, G64_SMEM);
    cudaFuncSetAttribute(proj_gemm64, cudaFuncAttributeMaxDynamicSharedMemorySize, G64_SMEM);

    // 1. fused prep: x convert + both W transposes (3072 blocks)
    prep_fused<<<3072, 256>>>(x, (__half*)p_xh, Wqkv, (__half*)p_wqt, Wproj, (__half*)p_wpt);

    // 2. QKV GEMM (single fp16, BM=64, occ 3): 768 CTAs
    qkv_gemm64<<<dim3(12, NROW / 64), 256, G64_SMEM>>>(
        (const __half*)p_xh, (const __half*)p_wqt, bqkv, (float*)p_qkv);

    // 3. fused: topk + sparse attention + tau_new (256 thr)
    attn_topk_fused<<<NROW, 256>>>(tau, out_tau);

    // 4. proj GEMM (single fp16, BM=64): 256 CTAs, single wave
    proj_gemm64<<<dim3(CC / 128, NROW / 64), 256, G64_SMEM>>>(
        (const __half*)p_ao, (const __half*)p_wpt, bproj, out_main);
}